// round 13
// baseline (speedup 1.0000x reference)
#include <cuda_runtime.h>
#include <math.h>

#define BATCH   32
#define SEQ     12
#define FEAT    128
#define KHEADS  8
#define HDIM    64
#define CDIM    64
#define NNODE   512
#define WF_COLS (NNODE * CDIM)    // 32768 floats per Wf row
#define NPROD   16                // producer blocks (2 batches each, shared W)
#define NCONS   128               // consumer blocks (2 per Wf row)
// grid = 144 <= 148 SMs -> single wave (spin handshake safe)

// Inter-block handshake state (zero-init; reset before kernel exit)
__device__ float    g_who[BATCH * CDIM];
__device__ float    g_half[CDIM * CDIM];   // hh=1 partial row sums
__device__ unsigned g_hflag[CDIM];         // per-row half-ready flags
__device__ unsigned g_ready;               // producers completed (0..16)
__device__ unsigned g_done;                // hh=0 consumers completed (0..64)

// ---------------------------------------------------------------------------
// One fused kernel, 144 blocks x 512 threads — SINGLE WAVE:
//   blocks 0..15   : producers — each computes who[] for TWO batches with
//                    every W_heads/W_out element loaded ONCE (dual accs),
//                    halving L1 ingress vs independent half-blocks.
//   blocks 16..143 : consumers — pair (cp, hh) streams half a Wf row
//                    (64 KB, front-batched float4); hh=1 publishes partial;
//                    hh=0 combines, waits for who, emits out[:, cp] fused.
// Attention blocks are exactly identity (all N nodes identical -> softmax
// uniform -> att @ Wh == Wh); a1*/a2* inputs are mathematically dead.
// ---------------------------------------------------------------------------
__global__ __launch_bounds__(512, 1) void fused_kernel(
    const float* __restrict__ x,         // (32,12,128)
    const float* __restrict__ W_heads,   // (8,128,64)
    const float* __restrict__ W_out,     // (512,64)
    const float* __restrict__ Wf,        // (64,32768)
    const float* __restrict__ bf,        // (64)
    float* __restrict__ out)             // (32,64)
{
    const int t = threadIdx.x;
    __shared__ float4 redA[512];         // 8 KB (also consumer's reducer)
    __shared__ float4 redB[512];         // 8 KB (producer batch-1 reducer)

    if (blockIdx.x < NPROD) {
        // ====== producer: batches b0=2*bid, b1=2*bid+1, shared W loads =====
        const int b0 = blockIdx.x * 2;
        __shared__ float s_x[2][FEAT];
        __shared__ float s_h[2][KHEADS * HDIM];

        if (t < 256) {
            const int hb = t >> 7, f = t & 127;
            s_x[hb][f] = x[((size_t)(b0 + hb) * SEQ + (SEQ - 1)) * FEAT + f];
        }
        __syncthreads();

        // Wh: 128 (k,h4) float4 outputs x 2 batches; 4 subs split f (32 ea);
        // each W float4 loaded once, FMA'd into BOTH batch accumulators.
        {
            const int p   = t >> 2;      // k*16 + h4
            const int sub = t & 3;
            const int k   = p >> 4;
            const int h4  = p & 15;
            const int f0  = sub * 32;
            const float4* Wp = reinterpret_cast<const float4*>(W_heads)
                               + (k * FEAT + f0) * 16 + h4;
            float4 a0 = make_float4(0.f, 0.f, 0.f, 0.f);
            float4 a1 = make_float4(0.f, 0.f, 0.f, 0.f);
#pragma unroll
            for (int blk = 0; blk < 4; blk++) {
                float4 w[8];
#pragma unroll
                for (int j = 0; j < 8; j++)
                    w[j] = Wp[(blk * 8 + j) * 16];
#pragma unroll
                for (int j = 0; j < 8; j++) {
                    const int f = f0 + blk * 8 + j;
                    const float x0 = s_x[0][f], x1 = s_x[1][f];
                    a0.x += x0 * w[j].x; a0.y += x0 * w[j].y;
                    a0.z += x0 * w[j].z; a0.w += x0 * w[j].w;
                    a1.x += x1 * w[j].x; a1.y += x1 * w[j].y;
                    a1.z += x1 * w[j].z; a1.w += x1 * w[j].w;
                }
            }
            redA[t] = a0;
            redB[t] = a1;
        }
        __syncthreads();
        if (t < 256) {
            const int hb = t >> 7, tt = t & 127;     // tt = p
            const float4* R = hb ? redB : redA;
            float4 a = R[4*tt], b1 = R[4*tt+1], c1 = R[4*tt+2], d = R[4*tt+3];
            float v0 = a.x + b1.x + c1.x + d.x;
            float v1 = a.y + b1.y + c1.y + d.y;
            float v2 = a.z + b1.z + c1.z + d.z;
            float v3 = a.w + b1.w + c1.w + d.w;
            s_h[hb][4*tt+0] = (v0 > 0.f) ? v0 : expm1f(v0);   // elu
            s_h[hb][4*tt+1] = (v1 > 0.f) ? v1 : expm1f(v1);
            s_h[hb][4*tt+2] = (v2 > 0.f) ? v2 : expm1f(v2);
            s_h[hb][4*tt+3] = (v3 > 0.f) ? v3 : expm1f(v3);
        }
        __syncthreads();

        // Wh_o: 16 c-float4 x 2 batches; 32 groups split f (16 ea);
        // W_out loaded once, dual accumulators.
        {
            const int c4  = t & 15;
            const int grp = t >> 4;
            const float4* Wo = reinterpret_cast<const float4*>(W_out)
                               + grp * 16 * 16 + c4;
            float4 a0 = make_float4(0.f, 0.f, 0.f, 0.f);
            float4 a1 = make_float4(0.f, 0.f, 0.f, 0.f);
#pragma unroll
            for (int blk = 0; blk < 2; blk++) {
                float4 w[8];
#pragma unroll
                for (int j = 0; j < 8; j++)
                    w[j] = Wo[(blk * 8 + j) * 16];
#pragma unroll
                for (int j = 0; j < 8; j++) {
                    const int f = grp * 16 + blk * 8 + j;
                    const float h0 = s_h[0][f], h1 = s_h[1][f];
                    a0.x += h0 * w[j].x; a0.y += h0 * w[j].y;
                    a0.z += h0 * w[j].z; a0.w += h0 * w[j].w;
                    a1.x += h1 * w[j].x; a1.y += h1 * w[j].y;
                    a1.z += h1 * w[j].z; a1.w += h1 * w[j].w;
                }
            }
            redA[t] = a0;
            redB[t] = a1;
        }
        __syncthreads();
#pragma unroll
        for (int off = 256; off >= 16; off >>= 1) {
            if (t < off) {
                float4 a = redA[t], bv = redA[t + off];
                a.x += bv.x; a.y += bv.y; a.z += bv.z; a.w += bv.w;
                redA[t] = a;
                float4 c = redB[t], dv = redB[t + off];
                c.x += dv.x; c.y += dv.y; c.z += dv.z; c.w += dv.w;
                redB[t] = c;
            }
            __syncthreads();
        }
        if (t < 16) {
            reinterpret_cast<float4*>(g_who)[(b0    ) * 16 + t] = redA[t];
            reinterpret_cast<float4*>(g_who)[(b0 + 1) * 16 + t] = redB[t];
        }
        __syncthreads();
        if (t == 0) {
            __threadfence();                 // release g_who (cumulative)
            atomicAdd(&g_ready, 1u);
        }
    } else {
        // ============== consumer: half-row (cp, hh) of Wf ===============
        const int idx = blockIdx.x - NPROD;  // 0..127
        const int cp  = idx >> 1;            // 0..63
        const int hh  = idx & 1;             // which 256 n's

        // stream + reduce 64 KB: 8-deep front-batched float4 per thread
        {
            const float4* row = reinterpret_cast<const float4*>(
                Wf + (size_t)cp * WF_COLS);
            const int c4  = t & 15;
            const int grp = t >> 4;          // 0..31, each 8 n's
            const int n0  = hh * 256 + grp * 8;
            float4 v[8];
#pragma unroll
            for (int j = 0; j < 8; j++)
                v[j] = row[(n0 + j) * 16 + c4];
#pragma unroll
            for (int s = 4; s >= 1; s >>= 1)
#pragma unroll
                for (int j = 0; j < s; j++) {
                    v[j].x += v[j + s].x; v[j].y += v[j + s].y;
                    v[j].z += v[j + s].z; v[j].w += v[j + s].w;
                }
            redA[t] = v[0];
        }
        __syncthreads();
#pragma unroll
        for (int off = 256; off >= 16; off >>= 1) {
            if (t < off) {
                float4 a = redA[t], bv = redA[t + off];
                a.x += bv.x; a.y += bv.y; a.z += bv.z; a.w += bv.w;
                redA[t] = a;
            }
            __syncthreads();
        }

        if (hh == 1) {
            // publish partial + release flag, then exit (never spins)
            if (t < 16)
                reinterpret_cast<float4*>(g_half)[cp * 16 + t] = redA[t];
            __syncthreads();
            if (t == 0) {
                __threadfence();
                atomicExch(&g_hflag[cp], 1u);
            }
            return;
        }

        // ---------------- hh == 0: combine + fused output ---------------
        __shared__ float s_wf[CDIM];
        __shared__ float s_who[BATCH * 65]; // padded: conflict-free dot

        if (t == 0) {
            volatile unsigned* fp = &g_hflag[cp];
            volatile unsigned* rp = &g_ready;
            while (*fp == 0u || *rp < NPROD) { __nanosleep(32); }
            __threadfence();                 // acquire g_half + g_who
            *fp = 0u;                        // reset for next replay
        }
        __syncthreads();

        if (t < 16) {
            const float4 a = redA[t];
            const float4 p = reinterpret_cast<const float4*>(g_half)[cp * 16 + t];
            s_wf[4*t+0] = a.x + p.x; s_wf[4*t+1] = a.y + p.y;
            s_wf[4*t+2] = a.z + p.z; s_wf[4*t+3] = a.w + p.w;
        }
        // stage who into padded smem (coalesced)
#pragma unroll
        for (int i = t; i < BATCH * CDIM; i += 512)
            s_who[(i >> 6) * 65 + (i & 63)] = g_who[i];
        __syncthreads();

        // fused final GEMV for this channel
        if (t < BATCH) {
            float acc = bf[cp];
#pragma unroll
            for (int c = 0; c < CDIM; c++)
                acc += s_who[t * 65 + c] * s_wf[c];
            out[(size_t)t * CDIM + cp] = acc;
        }
        __syncthreads();

        // last hh==0 consumer resets shared handshake state
        if (t == 0) {
            unsigned old = atomicAdd(&g_done, 1u);
            if (old == CDIM - 1) {
                g_ready = 0u;
                __threadfence();
                g_done = 0u;
            }
        }
    }
}

// ---------------------------------------------------------------------------
// Inputs (metadata order): 0:x 1:W_heads 2:a1_heads 3:a2_heads 4:W_out
// 5:a1_out 6:a2_out 7:Wf 8:bf.  Output float32 (32,64).
// ---------------------------------------------------------------------------
extern "C" void kernel_launch(void* const* d_in, const int* in_sizes, int n_in,
                              void* d_out, int out_size) {
    const float* x       = (const float*)d_in[0];
    const float* W_heads = (const float*)d_in[1];
    const float* W_out   = (const float*)d_in[4];
    const float* Wf      = (const float*)d_in[7];
    const float* bf      = (const float*)d_in[8];
    float* out = (float*)d_out;

    fused_kernel<<<NPROD + NCONS, 512>>>(x, W_heads, W_out, Wf, bf, out);
}

// round 14
// speedup vs baseline: 1.0266x; 1.0266x over previous
#include <cuda_runtime.h>
#include <math.h>

#define BATCH   32
#define SEQ     12
#define FEAT    128
#define KHEADS  8
#define HDIM    64
#define CDIM    64
#define NNODE   512
#define WF_COLS (NNODE * CDIM)    // 32768 floats per Wf row
#define NPROD   16                // producer blocks (2 batches each)
#define NCONS   128               // consumer blocks (2 per Wf row)
#define HALF_BYTES 65536u         // 64 KB = half of one Wf row
// grid = 144 <= 148 SMs -> single wave (spin handshake safe)

// Inter-block handshake state (zero-init; reset before kernel exit)
__device__ float    g_who[BATCH * CDIM];
__device__ float    g_half[CDIM * CDIM];   // hh=1 partial row sums
__device__ unsigned g_hflag[CDIM];         // per-row half-ready flags
__device__ unsigned g_ready;               // producers completed (0..16)
__device__ unsigned g_done;                // hh=0 consumers completed (0..64)

__device__ __forceinline__ unsigned smem_u32(const void* p) {
    unsigned a;
    asm("{ .reg .u64 t; cvta.to.shared.u64 t, %1; cvt.u32.u64 %0, t; }"
        : "=r"(a) : "l"(p));
    return a;
}

__device__ __forceinline__ void mbar_wait_parity(unsigned mbar, unsigned parity) {
    unsigned done;
    asm volatile(
        "{\n\t.reg .pred p;\n\t"
        "mbarrier.try_wait.parity.acquire.cta.shared::cta.b64 p, [%1], %2;\n\t"
        "selp.b32 %0, 1, 0, p;\n\t}"
        : "=r"(done) : "r"(mbar), "r"(parity) : "memory");
    if (!done) {
        asm volatile(
            "{\n\t.reg .pred P1;\n\t"
            "W_%=:\n\t"
            "mbarrier.try_wait.parity.acquire.cta.shared::cta.b64 P1, [%0], %1, 0x989680;\n\t"
            "@P1 bra.uni D_%=;\n\t"
            "bra.uni W_%=;\n\t"
            "D_%=:\n\t}"
            :: "r"(mbar), "r"(parity) : "memory");
    }
}

// ---------------------------------------------------------------------------
// One fused kernel, 144 blocks x 512 threads — SINGLE WAVE:
//   blocks 0..15   : producers (R12 form) — two 256-thread halves, each
//                    computes who[b] = elu(x_last @ W_heads) @ W_out.
//   blocks 16..143 : consumers — pair (cp, hh): ONE cp.async.bulk copies the
//                    64 KB half-row into smem (DMA path, not LDG), reduce
//                    from smem; hh=1 publishes partial; hh=0 combines, waits
//                    for who, emits out[:, cp] fused.
// Attention blocks are exactly identity (all N nodes identical -> softmax
// uniform -> att @ Wh == Wh); a1*/a2* inputs are mathematically dead.
// ---------------------------------------------------------------------------
__global__ __launch_bounds__(512, 1) void fused_kernel(
    const float* __restrict__ x,         // (32,12,128)
    const float* __restrict__ W_heads,   // (8,128,64)
    const float* __restrict__ W_out,     // (512,64)
    const float* __restrict__ Wf,        // (64,32768)
    const float* __restrict__ bf,        // (64)
    float* __restrict__ out)             // (32,64)
{
    const int t = threadIdx.x;
    extern __shared__ float4 stage[];    // 64 KB dynamic (consumers only)
    __shared__ float4 red[512];          // 8 KB reduction scratch

    if (blockIdx.x < NPROD) {
        // ============ producer: batches 2*bid and 2*bid+1 (R12) =========
        const int half = t >> 8;
        const int tt   = t & 255;
        const int b    = blockIdx.x * 2 + half;
        __shared__ float s_x[2][FEAT];
        __shared__ float s_h[2][KHEADS * HDIM];

        if (t < 256) {
            const int hb = t >> 7, f = t & 127;
            s_x[hb][f] = x[((size_t)(blockIdx.x * 2 + hb) * SEQ + (SEQ - 1))
                           * FEAT + f];
        }
        __syncthreads();

        // Wh: 128 (k,h4) float4 outputs per batch; 2 threads split f (64 ea)
        {
            const int p   = tt >> 1;
            const int sub = tt & 1;
            const int k   = p >> 4;
            const int h4  = p & 15;
            const int f0  = sub * 64;
            const float4* Wp = reinterpret_cast<const float4*>(W_heads)
                               + (k * FEAT + f0) * 16 + h4;
            float4 acc = make_float4(0.f, 0.f, 0.f, 0.f);
#pragma unroll
            for (int blk = 0; blk < 8; blk++) {
                float4 w[8];
#pragma unroll
                for (int j = 0; j < 8; j++)
                    w[j] = Wp[(blk * 8 + j) * 16];
#pragma unroll
                for (int j = 0; j < 8; j++) {
                    const float xv = s_x[half][f0 + blk * 8 + j];
                    acc.x += xv * w[j].x; acc.y += xv * w[j].y;
                    acc.z += xv * w[j].z; acc.w += xv * w[j].w;
                }
            }
            red[t] = acc;
        }
        __syncthreads();
        if (tt < 128) {
            const int base = half * 256;
            float4 a = red[base + 2 * tt], b1 = red[base + 2 * tt + 1];
            float v0 = a.x + b1.x, v1 = a.y + b1.y;
            float v2 = a.z + b1.z, v3 = a.w + b1.w;
            s_h[half][4*tt+0] = (v0 > 0.f) ? v0 : expm1f(v0);   // elu
            s_h[half][4*tt+1] = (v1 > 0.f) ? v1 : expm1f(v1);
            s_h[half][4*tt+2] = (v2 > 0.f) ? v2 : expm1f(v2);
            s_h[half][4*tt+3] = (v3 > 0.f) ? v3 : expm1f(v3);
        }
        __syncthreads();

        // Wh_o: 16 c-float4 outputs; 16 groups split the 512 f (32 each)
        {
            const int c4  = tt & 15;
            const int grp = tt >> 4;
            const float4* Wo = reinterpret_cast<const float4*>(W_out)
                               + grp * 32 * 16 + c4;
            float4 acc = make_float4(0.f, 0.f, 0.f, 0.f);
#pragma unroll
            for (int blk = 0; blk < 4; blk++) {
                float4 w[8];
#pragma unroll
                for (int j = 0; j < 8; j++)
                    w[j] = Wo[(blk * 8 + j) * 16];
#pragma unroll
                for (int j = 0; j < 8; j++) {
                    const float hv = s_h[half][grp * 32 + blk * 8 + j];
                    acc.x += hv * w[j].x; acc.y += hv * w[j].y;
                    acc.z += hv * w[j].z; acc.w += hv * w[j].w;
                }
            }
            red[t] = acc;
        }
        __syncthreads();
#pragma unroll
        for (int off = 128; off >= 16; off >>= 1) {
            if (tt < off) {
                const int base = half * 256;
                float4 a = red[base + tt], bv = red[base + tt + off];
                a.x += bv.x; a.y += bv.y; a.z += bv.z; a.w += bv.w;
                red[base + tt] = a;
            }
            __syncthreads();
        }
        if (tt < 16)
            reinterpret_cast<float4*>(g_who)[b * 16 + tt] = red[half * 256 + tt];
        __syncthreads();
        if (t == 0) {
            __threadfence();                 // release g_who (cumulative)
            atomicAdd(&g_ready, 1u);
        }
    } else {
        // ============== consumer: half-row (cp, hh) of Wf ===============
        const int idx = blockIdx.x - NPROD;  // 0..127
        const int cp  = idx >> 1;            // 0..63
        const int hh  = idx & 1;             // which 256 n's

        __shared__ unsigned long long s_mbar;
        const unsigned mbar = smem_u32(&s_mbar);

        if (t == 0) {
            asm volatile("mbarrier.init.shared.b64 [%0], %1;"
                         :: "r"(mbar), "r"(1u) : "memory");
        }
        __syncthreads();

        if (t == 0) {
            asm volatile("mbarrier.arrive.expect_tx.shared.b64 _, [%0], %1;"
                         :: "r"(mbar), "r"(HALF_BYTES) : "memory");
            const void* src = (const char*)(Wf + (size_t)cp * WF_COLS)
                              + (size_t)hh * HALF_BYTES;
            // one 64 KB bulk DMA: DRAM -> smem, completion via mbarrier tx
            asm volatile(
                "cp.async.bulk.shared::cta.global.mbarrier::complete_tx::bytes "
                "[%0], [%1], %2, [%3];"
                :: "r"(smem_u32(stage)), "l"(src), "r"(HALF_BYTES), "r"(mbar)
                : "memory");
        }
        mbar_wait_parity(mbar, 0u);

        // reduce 4096 float4 from smem: 8 per thread; c4 = t&15 invariant
        {
            float4 v[8];
#pragma unroll
            for (int j = 0; j < 8; j++)
                v[j] = stage[t + 512 * j];
#pragma unroll
            for (int s = 4; s >= 1; s >>= 1)
#pragma unroll
                for (int j = 0; j < s; j++) {
                    v[j].x += v[j + s].x; v[j].y += v[j + s].y;
                    v[j].z += v[j + s].z; v[j].w += v[j + s].w;
                }
            red[t] = v[0];
        }
        __syncthreads();
#pragma unroll
        for (int off = 256; off >= 16; off >>= 1) {
            if (t < off) {
                float4 a = red[t], bv = red[t + off];
                a.x += bv.x; a.y += bv.y; a.z += bv.z; a.w += bv.w;
                red[t] = a;
            }
            __syncthreads();
        }

        if (hh == 1) {
            // publish partial + release flag, then exit (never spins)
            if (t < 16)
                reinterpret_cast<float4*>(g_half)[cp * 16 + t] = red[t];
            __syncthreads();
            if (t == 0) {
                __threadfence();
                atomicExch(&g_hflag[cp], 1u);
            }
            return;
        }

        // ---------------- hh == 0: combine + fused output ---------------
        __shared__ float s_wf[CDIM];
        __shared__ float s_who[BATCH * 65]; // padded: conflict-free dot

        if (t == 0) {
            volatile unsigned* fp = &g_hflag[cp];
            volatile unsigned* rp = &g_ready;
            while (*fp == 0u || *rp < NPROD) { __nanosleep(32); }
            __threadfence();                 // acquire g_half + g_who
            *fp = 0u;                        // reset for next replay
        }
        __syncthreads();

        if (t < 16) {
            const float4 a = red[t];
            const float4 p = reinterpret_cast<const float4*>(g_half)[cp * 16 + t];
            s_wf[4*t+0] = a.x + p.x; s_wf[4*t+1] = a.y + p.y;
            s_wf[4*t+2] = a.z + p.z; s_wf[4*t+3] = a.w + p.w;
        }
        // stage who into padded smem (coalesced)
#pragma unroll
        for (int i = t; i < BATCH * CDIM; i += 512)
            s_who[(i >> 6) * 65 + (i & 63)] = g_who[i];
        __syncthreads();

        // fused final GEMV for this channel
        if (t < BATCH) {
            float acc = bf[cp];
#pragma unroll
            for (int c = 0; c < CDIM; c++)
                acc += s_who[t * 65 + c] * s_wf[c];
            out[(size_t)t * CDIM + cp] = acc;
        }
        __syncthreads();

        // last hh==0 consumer resets shared handshake state
        if (t == 0) {
            unsigned old = atomicAdd(&g_done, 1u);
            if (old == CDIM - 1) {
                g_ready = 0u;
                __threadfence();
                g_done = 0u;
            }
        }
    }
}

// ---------------------------------------------------------------------------
// Inputs (metadata order): 0:x 1:W_heads 2:a1_heads 3:a2_heads 4:W_out
// 5:a1_out 6:a2_out 7:Wf 8:bf.  Output float32 (32,64).
// ---------------------------------------------------------------------------
extern "C" void kernel_launch(void* const* d_in, const int* in_sizes, int n_in,
                              void* d_out, int out_size) {
    const float* x       = (const float*)d_in[0];
    const float* W_heads = (const float*)d_in[1];
    const float* W_out   = (const float*)d_in[4];
    const float* Wf      = (const float*)d_in[7];
    const float* bf      = (const float*)d_in[8];
    float* out = (float*)d_out;

    // host-side attribute (not an allocation; idempotent; capture-safe)
    cudaFuncSetAttribute(fused_kernel,
                         cudaFuncAttributeMaxDynamicSharedMemorySize,
                         (int)HALF_BYTES);
    fused_kernel<<<NPROD + NCONS, 512, HALF_BYTES>>>(
        x, W_heads, W_out, Wf, bf, out);
}